// round 6
// baseline (speedup 1.0000x reference)
#include <cuda_runtime.h>
#include <cuda_fp16.h>
#include <cstdint>

#define BS   16
#define N1   4096
#define N2   1024
#define C1   128
#define C2   256
#define CH   256
#define COUT 256

// Scratch (static device globals -- no allocation)
__device__ int    g_idx[BS * N1 * 3];
__device__ float  g_wts[BS * N1 * 3];
__device__ float  g_G2 [BS * N2 * CH];                 // fea2 @ W1b (fp32)
__device__ __align__(16) __half g_Wt1[CH * (C1 + C2)]; // W1^T [256][384] fp16
__device__ __align__(16) __half g_Wt2[COUT * CH];      // W2^T [256][256] fp16

// ---------------------------------------------------------------------------
__device__ __forceinline__ uint32_t smem_u32(const void* p) {
    uint32_t a;
    asm("{ .reg .u64 t; cvta.to.shared.u64 t, %1; cvt.u32.u64 %0, t; }"
        : "=r"(a) : "l"(p));
    return a;
}
__device__ __forceinline__ void ldm_x4(uint32_t r[4], uint32_t addr) {
    asm volatile("ldmatrix.sync.aligned.m8n8.x4.shared.b16 {%0,%1,%2,%3}, [%4];"
                 : "=r"(r[0]), "=r"(r[1]), "=r"(r[2]), "=r"(r[3]) : "r"(addr));
}
__device__ __forceinline__ void mma_f16(float c[4], const uint32_t a[4],
                                        const uint32_t b[2]) {
    asm volatile(
        "mma.sync.aligned.m16n8k16.row.col.f32.f16.f16.f32 "
        "{%0,%1,%2,%3}, {%4,%5,%6,%7}, {%8,%9}, {%0,%1,%2,%3};\n"
        : "+f"(c[0]), "+f"(c[1]), "+f"(c[2]), "+f"(c[3])
        : "r"(a[0]), "r"(a[1]), "r"(a[2]), "r"(a[3]), "r"(b[0]), "r"(b[1]));
}
#define CP16(dst, src) \
    asm volatile("cp.async.cg.shared.global [%0], [%1], 16;" :: "r"(dst), "l"(src))
#define CP_COMMIT() asm volatile("cp.async.commit_group;" ::: "memory")
#define CP_WAIT(n)  asm volatile("cp.async.wait_group %0;" :: "n"(n) : "memory")
#define SWZ(off, r) ((off) ^ (((r) & 7) << 4))

// ---------------------------------------------------------------------------
// Prep: transpose both weight matrices to fp16 K-major in one launch.
// region 0: W1 [384][256] -> Wt1 [256][384]; region 1: W2 [256][256] -> Wt2
// ---------------------------------------------------------------------------
__global__ __launch_bounds__(256) void prep_kernel(
    const float* __restrict__ W1, const float* __restrict__ W2,
    __half* __restrict__ Wt1, __half* __restrict__ Wt2)
{
    int i = blockIdx.x * 256 + threadIdx.x;
    if (i < 384 * 256) {
        int k = i >> 8, n = i & 255;
        Wt1[n * 384 + k] = __float2half_rn(W1[i]);
    } else {
        int j = i - 384 * 256;
        if (j < 256 * 256) {
            int k = j >> 8, n = j & 255;
            Wt2[n * 256 + k] = __float2half_rn(W2[j]);
        }
    }
}

// ---------------------------------------------------------------------------
// Combined kernel: blocks [0,256) run g2 GEMM (G2 = fea2 @ W1b),
// blocks [256,512) run 3-NN search. Independent work, overlapped on chip.
// 256 threads, 64 KB dynamic smem (g2 uses all; knn uses 12 KB).
// ---------------------------------------------------------------------------
#define PRE_SMEM 65536

__global__ __launch_bounds__(256, 2) void pre_kernel(
    const float* __restrict__ fea2, const __half* __restrict__ Wt1,
    float* __restrict__ G2,
    const float* __restrict__ xyz1, const float* __restrict__ xyz2,
    int* __restrict__ idx, float* __restrict__ wts)
{
    extern __shared__ __align__(1024) char smem[];
    const int tid = threadIdx.x;

    if (blockIdx.x < 256) {
        // ================= g2 GEMM: CTA 128x128, BK=64, K=256 =================
        const int lane = tid & 31, w = tid >> 5;
        const int wm = (w >> 2) * 64, wn = (w & 3) * 32;
        const int quad = lane >> 2, tq = lane & 3;
        const int row0 = (blockIdx.x >> 1) * 128;
        const int col0 = (blockIdx.x & 1) * 128;

        float acc[4][4][4];
        #pragma unroll
        for (int ma = 0; ma < 4; ma++)
            #pragma unroll
            for (int na = 0; na < 4; na++)
                #pragma unroll
                for (int q = 0; q < 4; q++) acc[ma][na][q] = 0.0f;

        auto fillA = [&](int k0, char* dst) {
            #pragma unroll
            for (int l = 0; l < 8; l++) {
                int f = tid + l * 256;
                int r = f >> 4, c4 = (f & 15) << 2;
                float4 v = *reinterpret_cast<const float4*>(
                    fea2 + (size_t)(row0 + r) * C2 + k0 + c4);
                __half2 h0 = __floats2half2_rn(v.x, v.y);
                __half2 h1 = __floats2half2_rn(v.z, v.w);
                uint2 u;
                u.x = *reinterpret_cast<uint32_t*>(&h0);
                u.y = *reinterpret_cast<uint32_t*>(&h1);
                *reinterpret_cast<uint2*>(dst + SWZ(r * 128 + c4 * 2, r)) = u;
            }
        };
        auto fillB = [&](int k0, uint32_t dstu) {
            #pragma unroll
            for (int l = 0; l < 4; l++) {
                int f = tid + l * 256;
                int r = f >> 3, c8 = (f & 7) << 3;
                CP16(dstu + SWZ(r * 128 + c8 * 2, r),
                     Wt1 + (size_t)(col0 + r) * 384 + 128 + k0 + c8);
            }
        };

        const int t8 = lane >> 3, rr = lane & 7;
        const int a_row_l = (t8 & 1) * 8 + rr, a_k8 = (t8 >> 1) * 8;
        const int b_n_l   = (t8 >> 1) * 8 + rr, b_k8 = (t8 & 1) * 8;
        uint32_t sbase = smem_u32(smem);

        fillA(0, smem);
        fillB(0, sbase + 16384);
        CP_COMMIT();

        #pragma unroll
        for (int i = 0; i < 4; i++) {
            CP_WAIT(0);
            __syncthreads();
            if (i + 1 < 4) {
                char* nb = smem + ((i + 1) & 1) * 32768;
                fillA((i + 1) << 6, nb);
                fillB((i + 1) << 6, sbase + ((i + 1) & 1) * 32768 + 16384);
                CP_COMMIT();
            }
            uint32_t smA = sbase + (i & 1) * 32768;
            uint32_t smB = smA + 16384;
            #pragma unroll
            for (int kk = 0; kk < 64; kk += 16) {
                uint32_t a[4][4], b[4][2];
                #pragma unroll
                for (int ma = 0; ma < 4; ma++) {
                    int row = wm + ma * 16 + a_row_l;
                    ldm_x4(a[ma], smA + SWZ(row * 128 + (kk + a_k8) * 2, row));
                }
                #pragma unroll
                for (int p = 0; p < 2; p++) {
                    int n = wn + p * 16 + b_n_l;
                    uint32_t r4[4];
                    ldm_x4(r4, smB + SWZ(n * 128 + (kk + b_k8) * 2, n));
                    b[p * 2 + 0][0] = r4[0]; b[p * 2 + 0][1] = r4[1];
                    b[p * 2 + 1][0] = r4[2]; b[p * 2 + 1][1] = r4[3];
                }
                #pragma unroll
                for (int ma = 0; ma < 4; ma++)
                    #pragma unroll
                    for (int na = 0; na < 4; na++)
                        mma_f16(acc[ma][na], a[ma], b[na]);
            }
        }

        #pragma unroll
        for (int ma = 0; ma < 4; ma++) {
            int rlo = row0 + wm + ma * 16 + quad;
            int rhi = rlo + 8;
            #pragma unroll
            for (int na = 0; na < 4; na++) {
                int col = col0 + wn + na * 8 + 2 * tq;
                float2 s0, s1;
                s0.x = acc[ma][na][0]; s0.y = acc[ma][na][1];
                s1.x = acc[ma][na][2]; s1.y = acc[ma][na][3];
                *reinterpret_cast<float2*>(G2 + (size_t)rlo * 256 + col) = s0;
                *reinterpret_cast<float2*>(G2 + (size_t)rhi * 256 + col) = s1;
            }
        }
    } else {
        // ================= 3-NN + inverse-distance weights =================
        float* sx = reinterpret_cast<float*>(smem);
        float* sy = sx + N2;
        float* sz = sy + N2;
        int i = blockIdx.x - 256;
        int b = i >> 4;
        const float* x2 = xyz2 + (size_t)b * N2 * 3;
        for (int j = tid; j < N2; j += 256) {
            sx[j] = x2[3 * j + 0];
            sy[j] = x2[3 * j + 1];
            sz[j] = x2[3 * j + 2];
        }
        __syncthreads();

        int p = (i & 15) * 256 + tid;
        size_t gp = (size_t)b * N1 + p;
        float px = xyz1[gp * 3 + 0];
        float py = xyz1[gp * 3 + 1];
        float pz = xyz1[gp * 3 + 2];

        float d0 = 3.4e38f, d1 = 3.4e38f, d2 = 3.4e38f;
        int   i0 = 0, i1 = 0, i2 = 0;
        #pragma unroll 4
        for (int j = 0; j < N2; j++) {
            float dx = px - sx[j], dy = py - sy[j], dz = pz - sz[j];
            float d = fmaf(dx, dx, fmaf(dy, dy, dz * dz));
            if (d < d2) {
                if (d < d1) {
                    d2 = d1; i2 = i1;
                    if (d < d0) { d1 = d0; i1 = i0; d0 = d; i0 = j; }
                    else        { d1 = d;  i1 = j; }
                } else { d2 = d; i2 = j; }
            }
        }
        float r0 = 1.0f / (d0 + 1e-8f);
        float r1 = 1.0f / (d1 + 1e-8f);
        float r2 = 1.0f / (d2 + 1e-8f);
        float s  = 1.0f / (r0 + r1 + r2);
        idx[gp * 3 + 0] = i0;  wts[gp * 3 + 0] = r0 * s;
        idx[gp * 3 + 1] = i1;  wts[gp * 3 + 1] = r1 * s;
        idx[gp * 3 + 2] = i2;  wts[gp * 3 + 2] = r2 * s;
    }
}

// ---------------------------------------------------------------------------
// Fused layers 1+2, full-prefetch. CTA = 128 rows x 256 cols, 512 threads
// (4m x 4n warps, warp tile 32x64).
// SMEM map (224 KB):
//   [0,16K)    A0 (fea1 k0..63)   --+
//   [16K,32K)  A1 (fea1 k64..127)   | overlaid by H (128x256 fp16, 64 KB)
//   [32K,64K)  B1_0 (W1a k0..63)  --+   after phase-1 barrier
//   [64K,96K)  B1_1 (W1a k64..127)     (not overlaid)
//   [96K,224K) W2 chunks 0..3 (32 KB each), prefetched at kernel start
// Gather(G2) runs FIRST (acc init) so its latency overlaps the prefetch.
// Phase 2 has zero waits: H + W2 fully resident.
// ---------------------------------------------------------------------------
#define FUSED_SMEM 229376

__global__ __launch_bounds__(512, 1) void fused_mlp(
    const float* __restrict__ fea1, const __half* __restrict__ Wt1,
    const __half* __restrict__ Wt2, float* __restrict__ out,
    const float* __restrict__ b1, const float* __restrict__ b2,
    const float* __restrict__ G2, const int* __restrict__ idx,
    const float* __restrict__ wts)
{
    extern __shared__ __align__(1024) char smem[];
    uint32_t sbase = smem_u32(smem);
    const int tid  = threadIdx.x;
    const int lane = tid & 31, w = tid >> 5;
    const int wm   = (w >> 2) << 5;     // 0,32,64,96
    const int wn   = (w & 3) << 6;      // 0,64,128,192
    const int quad = lane >> 2, tq = lane & 3;
    const int row0 = blockIdx.x << 7;

    const int t8 = lane >> 3, rr = lane & 7;
    const int a_row_l = (t8 & 1) * 8 + rr, a_k8 = (t8 >> 1) * 8;
    const int b_n_l   = (t8 >> 1) * 8 + rr, b_k8 = (t8 & 1) * 8;

    const uint32_t SA0 = sbase;
    const uint32_t SB1 = sbase + 32768;
    const uint32_t SW2 = sbase + 98304;   // 96 KB
    const uint32_t SH  = sbase;           // overlay after phase 1

    // --- issue all cp.async up front: B1 step0, B1 step1, W2 c0..c3 ---
    auto cpB1 = [&](int k0, uint32_t dstu) {
        #pragma unroll
        for (int l = 0; l < 4; l++) {
            int f = tid + l * 512;
            int r = f >> 3, c8 = (f & 7) << 3;
            CP16(dstu + SWZ(r * 128 + c8 * 2, r), Wt1 + (size_t)r * 384 + k0 + c8);
        }
    };
    auto cpW2 = [&](int s, uint32_t dstu) {
        #pragma unroll
        for (int l = 0; l < 4; l++) {
            int f = tid + l * 512;
            int r = f >> 3, c8 = (f & 7) << 3;
            CP16(dstu + SWZ(r * 128 + c8 * 2, r), Wt2 + (size_t)r * 256 + s * 64 + c8);
        }
    };

    cpB1(0,  SB1);          CP_COMMIT();   // group 0
    cpB1(64, SB1 + 32768);  CP_COMMIT();   // group 1
    #pragma unroll
    for (int s = 0; s < 4; s++) { cpW2(s, SW2 + s * 32768); CP_COMMIT(); } // 2..5

    // --- A tiles: fp32 LDG -> fp16 STS (both steps) ---
    #pragma unroll
    for (int st = 0; st < 2; st++) {
        char* dst = smem + st * 16384;
        #pragma unroll
        for (int l = 0; l < 4; l++) {
            int f = tid + l * 512;
            int r = f >> 4, c4 = (f & 15) << 2;
            float4 v = *reinterpret_cast<const float4*>(
                fea1 + (size_t)(row0 + r) * C1 + st * 64 + c4);
            __half2 h0 = __floats2half2_rn(v.x, v.y);
            __half2 h1 = __floats2half2_rn(v.z, v.w);
            uint2 u;
            u.x = *reinterpret_cast<uint32_t*>(&h0);
            u.y = *reinterpret_cast<uint32_t*>(&h1);
            *reinterpret_cast<uint2*>(dst + SWZ(r * 128 + c4 * 2, r)) = u;
        }
    }

    // --- gather(G2): initialize accumulators with interp contribution ---
    float acc[2][8][4];
    #pragma unroll
    for (int ma = 0; ma < 2; ma++)
        #pragma unroll
        for (int na = 0; na < 8; na++)
            #pragma unroll
            for (int q = 0; q < 4; q++) acc[ma][na][q] = 0.0f;

    int colb[8];
    #pragma unroll
    for (int na = 0; na < 8; na++) colb[na] = wn + na * 8 + 2 * tq;

    #pragma unroll
    for (int ma = 0; ma < 2; ma++) {
        #pragma unroll
        for (int h = 0; h < 2; h++) {
            int gr = row0 + wm + ma * 16 + quad + h * 8;
            int bb = gr >> 12;
            const int*   ip = idx + (size_t)gr * 3;
            const float* wp = wts + (size_t)gr * 3;
            #pragma unroll
            for (int k = 0; k < 3; k++) {
                int   ii = ip[k];
                float wt = wp[k];
                const float* g = G2 + (size_t)((bb << 10) + ii) * CH;
                #pragma unroll
                for (int na = 0; na < 8; na++) {
                    float2 u = *reinterpret_cast<const float2*>(g + colb[na]);
                    acc[ma][na][2 * h + 0] = fmaf(wt, u.x, acc[ma][na][2 * h + 0]);
                    acc[ma][na][2 * h + 1] = fmaf(wt, u.y, acc[ma][na][2 * h + 1]);
                }
            }
        }
    }

    auto compute_step = [&](uint32_t smA, uint32_t smB) {
        #pragma unroll
        for (int kk = 0; kk < 64; kk += 16) {
            uint32_t a[2][4], b[8][2];
            #pragma unroll
            for (int ma = 0; ma < 2; ma++) {
                int row = wm + ma * 16 + a_row_l;
                ldm_x4(a[ma], smA + SWZ(row * 128 + (kk + a_k8) * 2, row));
            }
            #pragma unroll
            for (int p = 0; p < 4; p++) {
                int n = wn + p * 16 + b_n_l;
                uint32_t r4[4];
                ldm_x4(r4, smB + SWZ(n * 128 + (kk + b_k8) * 2, n));
                b[p * 2 + 0][0] = r4[0]; b[p * 2 + 0][1] = r4[1];
                b[p * 2 + 1][0] = r4[2]; b[p * 2 + 1][1] = r4[3];
            }
            #pragma unroll
            for (int ma = 0; ma < 2; ma++)
                #pragma unroll
                for (int na = 0; na < 8; na++)
                    mma_f16(acc[ma][na], a[ma], b[na]);
        }
    };

    // ===== Phase 1 =====
    CP_WAIT(5);                 // group 0 (B1 step0) done
    __syncthreads();
    compute_step(SA0, SB1);
    CP_WAIT(4);                 // group 1 (B1 step1) done
    __syncthreads();
    compute_step(SA0 + 16384, SB1 + 32768);
    __syncthreads();            // all phase-1 smem reads complete

    // ---- epilogue 1: bias + relu -> fp16 H overlay [0, 64K) ----
    #pragma unroll
    for (int na = 0; na < 8; na++) {
        float2 bv = *reinterpret_cast<const float2*>(b1 + colb[na]);
        #pragma unroll
        for (int ma = 0; ma < 2; ma++) {
            acc[ma][na][0] = fmaxf(acc[ma][na][0] + bv.x, 0.0f);
            acc[ma][na][1] = fmaxf(acc[ma][na][1] + bv.y, 0.0f);
            acc[ma][na][2] = fmaxf(acc[ma][na][2] + bv.x, 0.0f);
            acc[ma][na][3] = fmaxf(acc[ma][na][3] + bv.y, 0.0f);
        }
    }
    #pragma unroll
    for (int ma = 0; ma < 2; ma++) {
        int rlo = wm + ma * 16 + quad;
        int rhi = rlo + 8;
        #pragma unroll
        for (int na = 0; na < 8; na++) {
            int col = colb[na];
            uint32_t choff = (col >> 6) * 16384;
            int cw2 = (col & 63) * 2;
            __half2 s0 = __floats2half2_rn(acc[ma][na][0], acc[ma][na][1]);
            __half2 s1 = __floats2half2_rn(acc[ma][na][2], acc[ma][na][3]);
            *reinterpret_cast<__half2*>(smem + choff + SWZ(rlo * 128 + cw2, rlo)) = s0;
            *reinterpret_cast<__half2*>(smem + choff + SWZ(rhi * 128 + cw2, rhi)) = s1;
        }
    }

    #pragma unroll
    for (int ma = 0; ma < 2; ma++)
        #pragma unroll
        for (int na = 0; na < 8; na++)
            #pragma unroll
            for (int q = 0; q < 4; q++) acc[ma][na][q] = 0.0f;

    CP_WAIT(0);                 // all W2 chunks resident
    __syncthreads();            // H writes visible

    // ===== Phase 2: 4 steps, no waits, all operands resident =====
    #pragma unroll
    for (int s = 0; s < 4; s++)
        compute_step(SH + s * 16384, SW2 + s * 32768);

    // ---- epilogue 2: bias + relu -> fp32 out ----
    #pragma unroll
    for (int na = 0; na < 8; na++) {
        float2 bv = *reinterpret_cast<const float2*>(b2 + colb[na]);
        #pragma unroll
        for (int ma = 0; ma < 2; ma++) {
            acc[ma][na][0] = fmaxf(acc[ma][na][0] + bv.x, 0.0f);
            acc[ma][na][1] = fmaxf(acc[ma][na][1] + bv.y, 0.0f);
            acc[ma][na][2] = fmaxf(acc[ma][na][2] + bv.x, 0.0f);
            acc[ma][na][3] = fmaxf(acc[ma][na][3] + bv.y, 0.0f);
        }
    }
    #pragma unroll
    for (int ma = 0; ma < 2; ma++) {
        int rlo = row0 + wm + ma * 16 + quad;
        int rhi = rlo + 8;
        #pragma unroll
        for (int na = 0; na < 8; na++) {
            float2 s0, s1;
            s0.x = acc[ma][na][0]; s0.y = acc[ma][na][1];
            s1.x = acc[ma][na][2]; s1.y = acc[ma][na][3];
            *reinterpret_cast<float2*>(out + (size_t)rlo * 256 + colb[na]) = s0;
            *reinterpret_cast<float2*>(out + (size_t)rhi * 256 + colb[na]) = s1;
        }
    }
}

// ---------------------------------------------------------------------------

extern "C" void kernel_launch(void* const* d_in, const int* in_sizes, int n_in,
                              void* d_out, int out_size)
{
    const float* xyz1 = (const float*)d_in[0];
    const float* xyz2 = (const float*)d_in[1];
    const float* fea1 = (const float*)d_in[2];
    const float* fea2 = (const float*)d_in[3];
    const float* W1   = (const float*)d_in[4];
    const float* b1   = (const float*)d_in[5];
    const float* W2   = (const float*)d_in[6];
    const float* b2   = (const float*)d_in[7];
    float* out = (float*)d_out;

    void *p_idx, *p_wts, *p_G2, *p_Wt1, *p_Wt2;
    cudaGetSymbolAddress(&p_idx, g_idx);
    cudaGetSymbolAddress(&p_wts, g_wts);
    cudaGetSymbolAddress(&p_G2,  g_G2);
    cudaGetSymbolAddress(&p_Wt1, g_Wt1);
    cudaGetSymbolAddress(&p_Wt2, g_Wt2);
    int*    idxp = (int*)p_idx;
    float*  wtsp = (float*)p_wts;
    float*  G2p  = (float*)p_G2;
    __half* Wt1p = (__half*)p_Wt1;
    __half* Wt2p = (__half*)p_Wt2;

    cudaFuncSetAttribute(pre_kernel, cudaFuncAttributeMaxDynamicSharedMemorySize, PRE_SMEM);
    cudaFuncSetAttribute(fused_mlp,  cudaFuncAttributeMaxDynamicSharedMemorySize, FUSED_SMEM);

    // 1) weight transposes (one tiny launch)
    prep_kernel<<<(384 * 256 + 256 * 256 + 255) / 256, 256>>>(W1, W2, Wt1p, Wt2p);

    // 2) concurrent: G2 = fea2 @ W1b  ||  3-NN search
    pre_kernel<<<512, 256, PRE_SMEM>>>(fea2, Wt1p, G2p, xyz1, xyz2, idxp, wtsp);

    // 3) fused: H = relu(fea1@W1a + gather(G2) + b1); out = relu(H@W2 + b2)
    fused_mlp<<<(BS * N1) / 128, 512, FUSED_SMEM>>>(
        fea1, Wt1p, Wt2p, out, b1, b2, G2p, idxp, wtsp);
}

// round 8
// speedup vs baseline: 1.1621x; 1.1621x over previous
#include <cuda_runtime.h>
#include <cuda_fp16.h>
#include <cstdint>

#define BS   16
#define N1   4096
#define N2   1024
#define C1   128
#define C2   256
#define CH   256
#define COUT 256

// Scratch (static device globals -- no allocation)
__device__ int    g_idx[BS * N1 * 3];
__device__ float  g_wts[BS * N1 * 3];
__device__ float  g_G2 [BS * N2 * CH];                 // fea2 @ W1b (fp32)
__device__ __align__(16) __half g_Wt1[CH * (C1 + C2)]; // W1^T [256][384] fp16
__device__ __align__(16) __half g_Wt2[COUT * CH];      // W2^T [256][256] fp16

// ---------------------------------------------------------------------------
__device__ __forceinline__ uint32_t smem_u32(const void* p) {
    uint32_t a;
    asm("{ .reg .u64 t; cvta.to.shared.u64 t, %1; cvt.u32.u64 %0, t; }"
        : "=r"(a) : "l"(p));
    return a;
}
__device__ __forceinline__ void ldm_x4(uint32_t r[4], uint32_t addr) {
    asm volatile("ldmatrix.sync.aligned.m8n8.x4.shared.b16 {%0,%1,%2,%3}, [%4];"
                 : "=r"(r[0]), "=r"(r[1]), "=r"(r[2]), "=r"(r[3]) : "r"(addr));
}
__device__ __forceinline__ void mma_f16(float c[4], const uint32_t a[4],
                                        const uint32_t b[2]) {
    asm volatile(
        "mma.sync.aligned.m16n8k16.row.col.f32.f16.f16.f32 "
        "{%0,%1,%2,%3}, {%4,%5,%6,%7}, {%8,%9}, {%0,%1,%2,%3};\n"
        : "+f"(c[0]), "+f"(c[1]), "+f"(c[2]), "+f"(c[3])
        : "r"(a[0]), "r"(a[1]), "r"(a[2]), "r"(a[3]), "r"(b[0]), "r"(b[1]));
}
#define CP16(dst, src) \
    asm volatile("cp.async.cg.shared.global [%0], [%1], 16;" :: "r"(dst), "l"(src))
#define CP_COMMIT() asm volatile("cp.async.commit_group;" ::: "memory")
#define CP_WAIT(n)  asm volatile("cp.async.wait_group %0;" :: "n"(n) : "memory")
#define SWZ(off, r) ((off) ^ (((r) & 7) << 4))

// ---------------------------------------------------------------------------
// Prep: transpose both weight matrices to fp16 K-major in one launch.
// ---------------------------------------------------------------------------
__global__ __launch_bounds__(256) void prep_kernel(
    const float* __restrict__ W1, const float* __restrict__ W2,
    __half* __restrict__ Wt1, __half* __restrict__ Wt2)
{
    int i = blockIdx.x * 256 + threadIdx.x;
    if (i < 384 * 256) {
        int k = i >> 8, n = i & 255;
        Wt1[n * 384 + k] = __float2half_rn(W1[i]);
    } else {
        int j = i - 384 * 256;
        if (j < 256 * 256) {
            int k = j >> 8, n = j & 255;
            Wt2[n * 256 + k] = __float2half_rn(W2[j]);
        }
    }
}

// ---------------------------------------------------------------------------
// Combined: blocks [0,256) g2 GEMM (G2 = fea2 @ W1b); [256,512) 3-NN search.
// ---------------------------------------------------------------------------
#define PRE_SMEM 65536

__global__ __launch_bounds__(256, 2) void pre_kernel(
    const float* __restrict__ fea2, const __half* __restrict__ Wt1,
    float* __restrict__ G2,
    const float* __restrict__ xyz1, const float* __restrict__ xyz2,
    int* __restrict__ idx, float* __restrict__ wts)
{
    extern __shared__ __align__(1024) char smem[];
    const int tid = threadIdx.x;

    if (blockIdx.x < 256) {
        const int lane = tid & 31, w = tid >> 5;
        const int wm = (w >> 2) * 64, wn = (w & 3) * 32;
        const int quad = lane >> 2, tq = lane & 3;
        const int row0 = (blockIdx.x >> 1) * 128;
        const int col0 = (blockIdx.x & 1) * 128;

        float acc[4][4][4];
        #pragma unroll
        for (int ma = 0; ma < 4; ma++)
            #pragma unroll
            for (int na = 0; na < 4; na++)
                #pragma unroll
                for (int q = 0; q < 4; q++) acc[ma][na][q] = 0.0f;

        auto fillA = [&](int k0, char* dst) {
            #pragma unroll
            for (int l = 0; l < 8; l++) {
                int f = tid + l * 256;
                int r = f >> 4, c4 = (f & 15) << 2;
                float4 v = *reinterpret_cast<const float4*>(
                    fea2 + (size_t)(row0 + r) * C2 + k0 + c4);
                __half2 h0 = __floats2half2_rn(v.x, v.y);
                __half2 h1 = __floats2half2_rn(v.z, v.w);
                uint2 u;
                u.x = *reinterpret_cast<uint32_t*>(&h0);
                u.y = *reinterpret_cast<uint32_t*>(&h1);
                *reinterpret_cast<uint2*>(dst + SWZ(r * 128 + c4 * 2, r)) = u;
            }
        };
        auto fillB = [&](int k0, uint32_t dstu) {
            #pragma unroll
            for (int l = 0; l < 4; l++) {
                int f = tid + l * 256;
                int r = f >> 3, c8 = (f & 7) << 3;
                CP16(dstu + SWZ(r * 128 + c8 * 2, r),
                     Wt1 + (size_t)(col0 + r) * 384 + 128 + k0 + c8);
            }
        };

        const int t8 = lane >> 3, rr = lane & 7;
        const int a_row_l = (t8 & 1) * 8 + rr, a_k8 = (t8 >> 1) * 8;
        const int b_n_l   = (t8 >> 1) * 8 + rr, b_k8 = (t8 & 1) * 8;
        uint32_t sbase = smem_u32(smem);

        fillA(0, smem);
        fillB(0, sbase + 16384);
        CP_COMMIT();

        #pragma unroll
        for (int i = 0; i < 4; i++) {
            CP_WAIT(0);
            __syncthreads();
            if (i + 1 < 4) {
                char* nb = smem + ((i + 1) & 1) * 32768;
                fillA((i + 1) << 6, nb);
                fillB((i + 1) << 6, sbase + ((i + 1) & 1) * 32768 + 16384);
                CP_COMMIT();
            }
            uint32_t smA = sbase + (i & 1) * 32768;
            uint32_t smB = smA + 16384;
            #pragma unroll
            for (int kk = 0; kk < 64; kk += 16) {
                uint32_t a[4][4], b[4][2];
                #pragma unroll
                for (int ma = 0; ma < 4; ma++) {
                    int row = wm + ma * 16 + a_row_l;
                    ldm_x4(a[ma], smA + SWZ(row * 128 + (kk + a_k8) * 2, row));
                }
                #pragma unroll
                for (int p = 0; p < 2; p++) {
                    int n = wn + p * 16 + b_n_l;
                    uint32_t r4[4];
                    ldm_x4(r4, smB + SWZ(n * 128 + (kk + b_k8) * 2, n));
                    b[p * 2 + 0][0] = r4[0]; b[p * 2 + 0][1] = r4[1];
                    b[p * 2 + 1][0] = r4[2]; b[p * 2 + 1][1] = r4[3];
                }
                #pragma unroll
                for (int ma = 0; ma < 4; ma++)
                    #pragma unroll
                    for (int na = 0; na < 4; na++)
                        mma_f16(acc[ma][na], a[ma], b[na]);
            }
        }

        #pragma unroll
        for (int ma = 0; ma < 4; ma++) {
            int rlo = row0 + wm + ma * 16 + quad;
            int rhi = rlo + 8;
            #pragma unroll
            for (int na = 0; na < 4; na++) {
                int col = col0 + wn + na * 8 + 2 * tq;
                float2 s0, s1;
                s0.x = acc[ma][na][0]; s0.y = acc[ma][na][1];
                s1.x = acc[ma][na][2]; s1.y = acc[ma][na][3];
                *reinterpret_cast<float2*>(G2 + (size_t)rlo * 256 + col) = s0;
                *reinterpret_cast<float2*>(G2 + (size_t)rhi * 256 + col) = s1;
            }
        }
    } else {
        float* sx = reinterpret_cast<float*>(smem);
        float* sy = sx + N2;
        float* sz = sy + N2;
        int i = blockIdx.x - 256;
        int b = i >> 4;
        const float* x2 = xyz2 + (size_t)b * N2 * 3;
        for (int j = tid; j < N2; j += 256) {
            sx[j] = x2[3 * j + 0];
            sy[j] = x2[3 * j + 1];
            sz[j] = x2[3 * j + 2];
        }
        __syncthreads();

        int p = (i & 15) * 256 + tid;
        size_t gp = (size_t)b * N1 + p;
        float px = xyz1[gp * 3 + 0];
        float py = xyz1[gp * 3 + 1];
        float pz = xyz1[gp * 3 + 2];

        float d0 = 3.4e38f, d1 = 3.4e38f, d2 = 3.4e38f;
        int   i0 = 0, i1 = 0, i2 = 0;
        #pragma unroll 4
        for (int j = 0; j < N2; j++) {
            float dx = px - sx[j], dy = py - sy[j], dz = pz - sz[j];
            float d = fmaf(dx, dx, fmaf(dy, dy, dz * dz));
            if (d < d2) {
                if (d < d1) {
                    d2 = d1; i2 = i1;
                    if (d < d0) { d1 = d0; i1 = i0; d0 = d; i0 = j; }
                    else        { d1 = d;  i1 = j; }
                } else { d2 = d; i2 = j; }
            }
        }
        float r0 = 1.0f / (d0 + 1e-8f);
        float r1 = 1.0f / (d1 + 1e-8f);
        float r2 = 1.0f / (d2 + 1e-8f);
        float s  = 1.0f / (r0 + r1 + r2);
        idx[gp * 3 + 0] = i0;  wts[gp * 3 + 0] = r0 * s;
        idx[gp * 3 + 1] = i1;  wts[gp * 3 + 1] = r1 * s;
        idx[gp * 3 + 2] = i2;  wts[gp * 3 + 2] = r2 * s;
    }
}

// ---------------------------------------------------------------------------
// Fused layers 1+2 at 2 CTAs/SM. CTA = 64 rows x 256 cols, 256 threads
// (8 warps, 2m x 4n, warp tile 32x64, acc = 64 fp32).
// SMEM (112 KB):
//   SA [0,16K)    A = fea1 tile, 2 chunks 64x64 fp16 (resident)
//   SB [16K,80K)  phase1: W1a chunks k0,k1 (32 KB each, cp.async)
//                 phase2: W2 double-buffer (overlay after phase-1 barrier)
//   SH [80K,112K) H tile 64x256 fp16, 4 chunks 64x64
// Gather(G2) = accumulator init, overlapped with A fill + B1 stream.
// ---------------------------------------------------------------------------
#define FUSED_SMEM 114688

__global__ __launch_bounds__(256, 2) void fused_mlp(
    const float* __restrict__ fea1, const __half* __restrict__ Wt1,
    const __half* __restrict__ Wt2, float* __restrict__ out,
    const float* __restrict__ b1, const float* __restrict__ b2,
    const float* __restrict__ G2, const int* __restrict__ idx,
    const float* __restrict__ wts)
{
    extern __shared__ __align__(1024) char smem[];
    uint32_t sbase = smem_u32(smem);
    const int tid  = threadIdx.x;
    const int lane = tid & 31, w = tid >> 5;
    const int wm   = (w >> 2) << 5;     // 0, 32
    const int wn   = (w & 3) << 6;      // 0, 64, 128, 192
    const int quad = lane >> 2, tq = lane & 3;
    const int row0 = blockIdx.x << 6;   // 64-row tiles

    const int t8 = lane >> 3, rr = lane & 7;
    const int a_row_l = (t8 & 1) * 8 + rr, a_k8 = (t8 >> 1) * 8;
    const int b_n_l   = (t8 >> 1) * 8 + rr, b_k8 = (t8 & 1) * 8;

    const uint32_t SA = sbase;
    const uint32_t SB = sbase + 16384;
    const uint32_t SH = sbase + 81920;

    // --- stream B1 chunks (cp.async, from L2-hot Wt1) ---
    auto cpB1 = [&](int s, uint32_t dstu) {
        #pragma unroll
        for (int l = 0; l < 8; l++) {
            int f = tid + l * 256;
            int r = f >> 3, c8 = (f & 7) << 3;
            CP16(dstu + SWZ(r * 128 + c8 * 2, r),
                 Wt1 + (size_t)r * 384 + s * 64 + c8);
        }
    };
    auto cpW2 = [&](int s, uint32_t dstu) {
        #pragma unroll
        for (int l = 0; l < 8; l++) {
            int f = tid + l * 256;
            int r = f >> 3, c8 = (f & 7) << 3;
            CP16(dstu + SWZ(r * 128 + c8 * 2, r),
                 Wt2 + (size_t)r * 256 + s * 64 + c8);
        }
    };

    cpB1(0, SB);          CP_COMMIT();   // group: B1 c0
    cpB1(1, SB + 32768);  CP_COMMIT();   // group: B1 c1

    // --- A tile: 64 rows x 128 k, fp32 LDG -> fp16 STS, 2 chunks of 64 ---
    #pragma unroll
    for (int l = 0; l < 8; l++) {
        int f = tid + l * 256;                 // 0..2047 float4s
        int r = f >> 5, c4 = (f & 31) << 2;    // row 0..63, col 0..124
        float4 v = *reinterpret_cast<const float4*>(
            fea1 + (size_t)(row0 + r) * C1 + c4);
        __half2 h0 = __floats2half2_rn(v.x, v.y);
        __half2 h1 = __floats2half2_rn(v.z, v.w);
        uint2 u;
        u.x = *reinterpret_cast<uint32_t*>(&h0);
        u.y = *reinterpret_cast<uint32_t*>(&h1);
        int chunk = c4 >> 6, cc = c4 & 63;
        *reinterpret_cast<uint2*>(smem + chunk * 8192 + SWZ(r * 128 + cc * 2, r)) = u;
    }

    // --- gather(G2): init accumulators with interp contribution ---
    float acc[2][8][4];
    #pragma unroll
    for (int ma = 0; ma < 2; ma++)
        #pragma unroll
        for (int na = 0; na < 8; na++)
            #pragma unroll
            for (int q = 0; q < 4; q++) acc[ma][na][q] = 0.0f;

    int colb[8];
    #pragma unroll
    for (int na = 0; na < 8; na++) colb[na] = wn + na * 8 + 2 * tq;

    #pragma unroll
    for (int ma = 0; ma < 2; ma++) {
        #pragma unroll
        for (int h = 0; h < 2; h++) {
            int gr = row0 + wm + ma * 16 + quad + h * 8;
            int bb = gr >> 12;
            const int*   ip = idx + (size_t)gr * 3;
            const float* wp = wts + (size_t)gr * 3;
            #pragma unroll
            for (int k = 0; k < 3; k++) {
                int   ii = ip[k];
                float wt = wp[k];
                const float* g = G2 + (size_t)((bb << 10) + ii) * CH;
                #pragma unroll
                for (int na = 0; na < 8; na++) {
                    float2 u = *reinterpret_cast<const float2*>(g + colb[na]);
                    acc[ma][na][2 * h + 0] = fmaf(wt, u.x, acc[ma][na][2 * h + 0]);
                    acc[ma][na][2 * h + 1] = fmaf(wt, u.y, acc[ma][na][2 * h + 1]);
                }
            }
        }
    }

    auto compute_step = [&](uint32_t smA, uint32_t smB) {
        #pragma unroll
        for (int kk = 0; kk < 64; kk += 16) {
            uint32_t a[2][4], b[8][2];
            #pragma unroll
            for (int ma = 0; ma < 2; ma++) {
                int row = wm + ma * 16 + a_row_l;
                ldm_x4(a[ma], smA + SWZ(row * 128 + (kk + a_k8) * 2, row));
            }
            #pragma unroll
            for (int p = 0; p < 4; p++) {
                int n = wn + p * 16 + b_n_l;
                uint32_t r4[4];
                ldm_x4(r4, smB + SWZ(n * 128 + (kk + b_k8) * 2, n));
                b[p * 2 + 0][0] = r4[0]; b[p * 2 + 0][1] = r4[1];
                b[p * 2 + 1][0] = r4[2]; b[p * 2 + 1][1] = r4[3];
            }
            #pragma unroll
            for (int ma = 0; ma < 2; ma++)
                #pragma unroll
                for (int na = 0; na < 8; na++)
                    mma_f16(acc[ma][na], a[ma], b[na]);
        }
    };

    // ===== Phase 1: K=128, 2 steps =====
    CP_WAIT(1);                  // B1 c0 resident
    __syncthreads();
    compute_step(SA, SB);
    CP_WAIT(0);                  // B1 c1 resident
    __syncthreads();
    compute_step(SA + 8192, SB + 32768);
    __syncthreads();             // all B1 reads done -> SB reusable

    // start W2 stream into SB overlay
    cpW2(0, SB);          CP_COMMIT();
    cpW2(1, SB + 32768);  CP_COMMIT();

    // ---- epilogue 1: bias + relu -> fp16 H in SH ----
    #pragma unroll
    for (int na = 0; na < 8; na++) {
        float2 bv = *reinterpret_cast<const float2*>(b1 + colb[na]);
        #pragma unroll
        for (int ma = 0; ma < 2; ma++) {
            acc[ma][na][0] = fmaxf(acc[ma][na][0] + bv.x, 0.0f);
            acc[ma][na][1] = fmaxf(acc[ma][na][1] + bv.y, 0.0f);
            acc[ma][na][2] = fmaxf(acc[ma][na][2] + bv.x, 0.0f);
            acc[ma][na][3] = fmaxf(acc[ma][na][3] + bv.y, 0.0f);
        }
    }
    #pragma unroll
    for (int ma = 0; ma < 2; ma++) {
        int rlo = wm + ma * 16 + quad;
        int rhi = rlo + 8;
        #pragma unroll
        for (int na = 0; na < 8; na++) {
            int col = colb[na];
            int choff = 81920 + (col >> 6) * 8192;
            int cw2 = (col & 63) * 2;
            __half2 s0 = __floats2half2_rn(acc[ma][na][0], acc[ma][na][1]);
            __half2 s1 = __floats2half2_rn(acc[ma][na][2], acc[ma][na][3]);
            *reinterpret_cast<__half2*>(smem + choff + SWZ(rlo * 128 + cw2, rlo)) = s0;
            *reinterpret_cast<__half2*>(smem + choff + SWZ(rhi * 128 + cw2, rhi)) = s1;
        }
    }

    #pragma unroll
    for (int ma = 0; ma < 2; ma++)
        #pragma unroll
        for (int na = 0; na < 8; na++)
            #pragma unroll
            for (int q = 0; q < 4; q++) acc[ma][na][q] = 0.0f;

    __syncthreads();             // H visible to all warps

    // ===== Phase 2: K=256, 4 steps, W2 double-buffered in SB =====
    #pragma unroll
    for (int s = 0; s < 4; s++) {
        if (s == 3) { CP_WAIT(0); }   // final chunk is the LAST commit
        else        { CP_WAIT(1); }
        __syncthreads();
        compute_step(SH + s * 8192, SB + (s & 1) * 32768);
        __syncthreads();         // buffer reads done before refill
        if (s + 2 < 4) {
            cpW2(s + 2, SB + (s & 1) * 32768);
            CP_COMMIT();
        }
    }

    // ---- epilogue 2: bias + relu -> fp32 out ----
    #pragma unroll
    for (int na = 0; na < 8; na++) {
        float2 bv = *reinterpret_cast<const float2*>(b2 + colb[na]);
        #pragma unroll
        for (int ma = 0; ma < 2; ma++) {
            acc[ma][na][0] = fmaxf(acc[ma][na][0] + bv.x, 0.0f);
            acc[ma][na][1] = fmaxf(acc[ma][na][1] + bv.y, 0.0f);
            acc[ma][na][2] = fmaxf(acc[ma][na][2] + bv.x, 0.0f);
            acc[ma][na][3] = fmaxf(acc[ma][na][3] + bv.y, 0.0f);
        }
    }
    #pragma unroll
    for (int ma = 0; ma < 2; ma++) {
        int rlo = row0 + wm + ma * 16 + quad;
        int rhi = rlo + 8;
        #pragma unroll
        for (int na = 0; na < 8; na++) {
            float2 s0, s1;
            s0.x = acc[ma][na][0]; s0.y = acc[ma][na][1];
            s1.x = acc[ma][na][2]; s1.y = acc[ma][na][3];
            *reinterpret_cast<float2*>(out + (size_t)rlo * 256 + colb[na]) = s0;
            *reinterpret_cast<float2*>(out + (size_t)rhi * 256 + colb[na]) = s1;
        }
    }
}

// ---------------------------------------------------------------------------

extern "C" void kernel_launch(void* const* d_in, const int* in_sizes, int n_in,
                              void* d_out, int out_size)
{
    const float* xyz1 = (const float*)d_in[0];
    const float* xyz2 = (const float*)d_in[1];
    const float* fea1 = (const float*)d_in[2];
    const float* fea2 = (const float*)d_in[3];
    const float* W1   = (const float*)d_in[4];
    const float* b1   = (const float*)d_in[5];
    const float* W2   = (const float*)d_in[6];
    const float* b2   = (const float*)d_in[7];
    float* out = (float*)d_out;

    void *p_idx, *p_wts, *p_G2, *p_Wt1, *p_Wt2;
    cudaGetSymbolAddress(&p_idx, g_idx);
    cudaGetSymbolAddress(&p_wts, g_wts);
    cudaGetSymbolAddress(&p_G2,  g_G2);
    cudaGetSymbolAddress(&p_Wt1, g_Wt1);
    cudaGetSymbolAddress(&p_Wt2, g_Wt2);
    int*    idxp = (int*)p_idx;
    float*  wtsp = (float*)p_wts;
    float*  G2p  = (float*)p_G2;
    __half* Wt1p = (__half*)p_Wt1;
    __half* Wt2p = (__half*)p_Wt2;

    cudaFuncSetAttribute(pre_kernel, cudaFuncAttributeMaxDynamicSharedMemorySize, PRE_SMEM);
    cudaFuncSetAttribute(fused_mlp,  cudaFuncAttributeMaxDynamicSharedMemorySize, FUSED_SMEM);

    // 1) weight transposes
    prep_kernel<<<(384 * 256 + 256 * 256 + 255) / 256, 256>>>(W1, W2, Wt1p, Wt2p);

    // 2) concurrent: G2 = fea2 @ W1b  ||  3-NN search
    pre_kernel<<<512, 256, PRE_SMEM>>>(fea2, Wt1p, G2p, xyz1, xyz2, idxp, wtsp);

    // 3) fused layers, 64-row tiles, 2 CTAs/SM
    fused_mlp<<<(BS * N1) / 64, 256, FUSED_SMEM>>>(
        fea1, Wt1p, Wt2p, out, b1, b2, G2p, idxp, wtsp);
}